// round 12
// baseline (speedup 1.0000x reference)
#include <cuda_runtime.h>

#define NB 32
#define NS 4096
#define ND 1024
#define NEGV -1e37f

#define SCHUNK 128
#define NCH (NS / SCHUNK)   // 32
#define QKB (NS / 8)        // 512 qk blocks per batch

// raw logits [B, S]
__device__ float g_logits[NB * NS];
// per-qk-block softmax stats: block max, block sum of exp(l - m_c)
__device__ float g_bm[NB * QKB];
__device__ float g_bs[NB * QKB];
// per-batch global max and 1/sum
__device__ float g_M[NB];
__device__ float g_invS[NB];
// partial PV sums [B, NCH, D]
__device__ float g_part[NB * NCH * ND];

// ---------------------------------------------------------------------------
// Kernel 1: logits[b,s] = q[b] . k[b,s]  (masked rows: skip K read, logit=NEG)
// 256 threads = 8 warps, each warp one s-row; q[b] staged in shared.
// K loads __ldcs (evict-first). Each block also emits (m_c, sum exp(l-m_c))
// over its 8 rows so no separate softmax pass over the logits is needed.
// ---------------------------------------------------------------------------
__global__ __launch_bounds__(256) void qk_kernel(
    const float* __restrict__ keys,
    const float* __restrict__ queries,
    const int* __restrict__ mask)
{
    int b  = blockIdx.x / QKB;
    int s0 = (blockIdx.x % QKB) * 8;

    __shared__ float4 qs[ND / 4];
    __shared__ float  larr[8];

    int t = threadIdx.x;
    qs[t] = ((const float4*)(queries + (size_t)b * ND))[t];
    __syncthreads();

    int warp = t >> 5;
    int lane = t & 31;
    int s = s0 + warp;

    bool valid = mask[b * NS + s] != 0;
    float acc = 0.f;
    if (valid) {
        const float4* k4 = (const float4*)(keys + ((size_t)b * NS + s) * ND);
#pragma unroll
        for (int i = 0; i < 8; i++) {
            int idx = i * 32 + lane;          // 0..255 float4s
            float4 kv = __ldcs(&k4[idx]);
            float4 qv = qs[idx];
            acc += kv.x * qv.x + kv.y * qv.y + kv.z * qv.z + kv.w * qv.w;
        }
#pragma unroll
        for (int o = 16; o; o >>= 1)
            acc += __shfl_xor_sync(0xFFFFFFFFu, acc, o);
    }
    float logit = valid ? acc : NEGV;
    if (lane == 0) {
        g_logits[b * NS + s] = logit;
        larr[warp] = logit;
    }
    __syncthreads();

    // warp 0: block stats over the 8 row logits
    if (warp == 0 && lane == 0) {
        float m = larr[0];
#pragma unroll
        for (int i = 1; i < 8; i++) m = fmaxf(m, larr[i]);
        float sum = 0.f;
#pragma unroll
        for (int i = 0; i < 8; i++) sum += __expf(larr[i] - m);
        int blk = blockIdx.x % QKB;
        g_bm[b * QKB + blk] = m;
        g_bs[b * QKB + blk] = sum;
    }
}

// ---------------------------------------------------------------------------
// Kernel 2: merge per-block stats -> per-batch M and 1/S.
// One block of 512 threads per batch (one thread per qk block).
// ---------------------------------------------------------------------------
__global__ __launch_bounds__(512) void merge_kernel()
{
    int b = blockIdx.x;
    int t = threadIdx.x;
    int warp = t >> 5;
    int lane = t & 31;

    float m_c = g_bm[b * QKB + t];
    float s_c = g_bs[b * QKB + t];

    __shared__ float red[16];

    // ---- global max ----
    float M = m_c;
#pragma unroll
    for (int o = 16; o; o >>= 1) M = fmaxf(M, __shfl_xor_sync(0xFFFFFFFFu, M, o));
    if (lane == 0) red[warp] = M;
    __syncthreads();
    if (t < 32) {
        float x = (lane < 16) ? red[lane] : NEGV;
#pragma unroll
        for (int o = 8; o; o >>= 1) x = fmaxf(x, __shfl_xor_sync(0xFFFFFFFFu, x, o));
        if (lane == 0) red[0] = x;
    }
    __syncthreads();
    M = red[0];
    __syncthreads();

    // ---- global sum ----
    float c = s_c * __expf(m_c - M);
#pragma unroll
    for (int o = 16; o; o >>= 1) c += __shfl_xor_sync(0xFFFFFFFFu, c, o);
    if (lane == 0) red[warp] = c;
    __syncthreads();
    if (t == 0) {
        float S = 0.f;
#pragma unroll
        for (int i = 0; i < 16; i++) S += red[i];
        g_M[b]    = M;
        g_invS[b] = 1.0f / S;
    }
}

// ---------------------------------------------------------------------------
// Kernel 3: partial PV. Block = (b, 128-row s-chunk), 1024 blocks total.
// Weights computed inline: w = exp(logit - M) * invS (masked rows -> exact 0,
// so their V rows are skipped). V loads __ldcs (evict-first).
// ---------------------------------------------------------------------------
__global__ __launch_bounds__(256) void pv_kernel(const float* __restrict__ values)
{
    int chunk = blockIdx.x & (NCH - 1);
    int b     = blockIdx.x / NCH;
    int s0    = chunk * SCHUNK;

    __shared__ float ws[SCHUNK];
    int t = threadIdx.x;
    if (t < SCHUNK) {
        float M    = g_M[b];
        float invS = g_invS[b];
        float l = g_logits[b * NS + s0 + t];
        ws[t] = __expf(l - M) * invS;       // masked: underflows to exactly 0
    }
    __syncthreads();

    const float4* v4 = (const float4*)(values + ((size_t)b * NS + s0) * ND);
    float4 acc = make_float4(0.f, 0.f, 0.f, 0.f);

#pragma unroll 4
    for (int i = 0; i < SCHUNK; i += 4) {
        float w0 = ws[i], w1 = ws[i + 1], w2 = ws[i + 2], w3 = ws[i + 3];
        float4 a = make_float4(0.f, 0.f, 0.f, 0.f);
        float4 c = make_float4(0.f, 0.f, 0.f, 0.f);
        float4 d = make_float4(0.f, 0.f, 0.f, 0.f);
        float4 e = make_float4(0.f, 0.f, 0.f, 0.f);
        if (w0 != 0.f) a = __ldcs(&v4[(size_t)(i + 0) * (ND / 4) + t]);
        if (w1 != 0.f) c = __ldcs(&v4[(size_t)(i + 1) * (ND / 4) + t]);
        if (w2 != 0.f) d = __ldcs(&v4[(size_t)(i + 2) * (ND / 4) + t]);
        if (w3 != 0.f) e = __ldcs(&v4[(size_t)(i + 3) * (ND / 4) + t]);
        acc.x += w0 * a.x; acc.y += w0 * a.y; acc.z += w0 * a.z; acc.w += w0 * a.w;
        acc.x += w1 * c.x; acc.y += w1 * c.y; acc.z += w1 * c.z; acc.w += w1 * c.w;
        acc.x += w2 * d.x; acc.y += w2 * d.y; acc.z += w2 * d.z; acc.w += w2 * d.w;
        acc.x += w3 * e.x; acc.y += w3 * e.y; acc.z += w3 * e.z; acc.w += w3 * e.w;
    }

    ((float4*)g_part)[(size_t)(b * NCH + chunk) * (ND / 4) + t] = acc;
}

// ---------------------------------------------------------------------------
// Kernel 4: out[b,:] = sum over 32 chunks of g_part[b,c,:].
// 256 blocks x 256 threads; 8 threads cooperate per float4 output
// (4 coalesced chunk-loads each), fixed-order combine via shared memory.
// ---------------------------------------------------------------------------
__global__ __launch_bounds__(256) void reduce_kernel(float* __restrict__ out)
{
    int t    = threadIdx.x;
    int oct  = t >> 5;                 // 0..7 chunk-octant
    int slot = t & 31;                 // 0..31 output slot within block
    int o  = blockIdx.x * 32 + slot;   // 0..8191 global float4 output index
    int b  = o >> 8;                   // ND/4 = 256 float4 per batch
    int d4 = o & 255;

    const float4* p4 = (const float4*)g_part + ((size_t)b * NCH) * (ND / 4) + d4;

    float4 acc = make_float4(0.f, 0.f, 0.f, 0.f);
#pragma unroll
    for (int c = 0; c < 4; c++) {
        float4 v = p4[(size_t)(oct * 4 + c) * (ND / 4)];
        acc.x += v.x; acc.y += v.y; acc.z += v.z; acc.w += v.w;
    }

    __shared__ float4 sp[7 * 32];      // octants 1..7
    if (oct > 0) sp[(oct - 1) * 32 + slot] = acc;
    __syncthreads();

    if (oct == 0) {
#pragma unroll
        for (int i = 0; i < 7; i++) {
            float4 v = sp[i * 32 + slot];
            acc.x += v.x; acc.y += v.y; acc.z += v.z; acc.w += v.w;
        }
        ((float4*)out)[o] = acc;
    }
}

// ---------------------------------------------------------------------------
extern "C" void kernel_launch(void* const* d_in, const int* in_sizes, int n_in,
                              void* d_out, int out_size)
{
    const float* keys    = (const float*)d_in[0];
    const float* queries = (const float*)d_in[1];
    const float* values  = (const float*)d_in[2];
    const int*   mask    = (const int*)d_in[3];
    float* out = (float*)d_out;

    qk_kernel<<<NB * QKB, 256>>>(keys, queries, mask);
    merge_kernel<<<NB, 512>>>();
    pv_kernel<<<NB * NCH, 256>>>(values);
    reduce_kernel<<<256, 256>>>(out);
}